// round 12
// baseline (speedup 1.0000x reference)
#include <cuda_runtime.h>
#include <cuda_bf16.h>
#include <cstdint>

#define N_NODES 100000
#define N_EDGES 1000000
#define IN_CH   128
#define OUT_CH  128
#define T_DIM   64
#define AGG_W   192

// ---------------- device scratch ----------------
__device__ __align__(16) float g_agg[(size_t)N_NODES * AGG_W];
__device__ __align__(16) float g_deg[N_NODES];
__device__ __align__(16) float g_cb[128];             // W_T_b + T_b
__device__ __align__(16) unsigned char g_bhi[5 * 16384];  // B hi, pre-swizzled chunk images
__device__ __align__(16) unsigned char g_blo[5 * 16384];  // B lo
__device__ int g_idx_is64;

// ---------------- generic helpers ----------------
__device__ __forceinline__ void red_add_v4(float* p, float4 v) {
    unsigned long long gp = __cvta_generic_to_global((void*)p);
    asm volatile("red.global.add.v4.f32 [%0], {%1,%2,%3,%4};"
                 :: "l"(gp), "f"(v.x), "f"(v.y), "f"(v.z), "f"(v.w)
                 : "memory");
}
__device__ __forceinline__ uint32_t smem_u32(const void* p) {
    uint32_t a;
    asm("{ .reg .u64 t; cvta.to.shared.u64 t, %1; cvt.u32.u64 %0, t; }"
        : "=r"(a) : "l"(p));
    return a;
}
#define SW128(o) ((o) ^ (((o) >> 3) & 0x70))

__device__ __forceinline__ void ldmx4(uint32_t addr, uint32_t& r0, uint32_t& r1,
                                      uint32_t& r2, uint32_t& r3) {
    asm volatile("ldmatrix.sync.aligned.m8n8.x4.shared.b16 {%0,%1,%2,%3}, [%4];"
                 : "=r"(r0), "=r"(r1), "=r"(r2), "=r"(r3) : "r"(addr));
}
__device__ __forceinline__ void mma_bf16(float* c, const uint32_t* a, const uint32_t* b) {
    asm volatile("mma.sync.aligned.m16n8k16.row.col.f32.bf16.bf16.f32 "
                 "{%0,%1,%2,%3}, {%4,%5,%6,%7}, {%8,%9}, {%0,%1,%2,%3};"
                 : "+f"(c[0]), "+f"(c[1]), "+f"(c[2]), "+f"(c[3])
                 : "r"(a[0]), "r"(a[1]), "r"(a[2]), "r"(a[3]), "r"(b[0]), "r"(b[1]));
}
__device__ __forceinline__ void cvt_split2(float a, float b, uint32_t& h, uint32_t& l) {
    __nv_bfloat162 hb = __floats2bfloat162_rn(a, b);
    float2 hf = __bfloat1622float2(hb);
    __nv_bfloat162 lb = __floats2bfloat162_rn(a - hf.x, b - hf.y);
    h = *(uint32_t*)&hb;
    l = *(uint32_t*)&lb;
}

// ---------------- kernel 0: detect edge_index dtype ----------------
__global__ void detect_kernel(const int* __restrict__ ei_raw) {
    __shared__ int any_nonzero;
    if (threadIdx.x == 0) any_nonzero = 0;
    __syncthreads();
    for (int i = threadIdx.x; i < 4096; i += blockDim.x)
        if (ei_raw[2 * i + 1] != 0) any_nonzero = 1;
    __syncthreads();
    if (threadIdx.x == 0) g_idx_is64 = (any_nonzero == 0);
}
__device__ __forceinline__ int load_idx(const void* ei_raw, size_t pos) {
    if (g_idx_is64) return (int)__ldg(&((const long long*)ei_raw)[pos]);
    return __ldg(&((const int*)ei_raw)[pos]);
}

// ---------------- kernel 1: combined bias ----------------
__global__ void prep_kernel(const float* __restrict__ Wtb, const float* __restrict__ Tb) {
    int tid = threadIdx.x;
    if (tid < 128) g_cb[tid] = Wtb[tid] + Tb[tid];
}

// ---------------- kernel 1b: precompute B bf16 hi/lo chunk images -----------
// image c (16KB) = SW128-swizzled [128 n-rows x 64 k] bf16, matching smem layout
__global__ void prep_b_kernel(const float* __restrict__ Wsw,
                              const float* __restrict__ Wtw,
                              const float* __restrict__ Tw) {
    int t = blockIdx.x * blockDim.x + threadIdx.x;
    if (t >= 5 * 1024) return;
    int c = t >> 10, rem = t & 1023;
    int n = rem >> 3, g = rem & 7;
    const float* bbase; int bstride;
    if (c < 2)      { bbase = Wsw + c * 64;       bstride = 128; }
    else if (c < 4) { bbase = Wtw + (c - 2) * 64; bstride = 128; }
    else            { bbase = Tw;                 bstride = 64;  }
    const float* p = bbase + (size_t)n * bstride + g * 8;
    float4 v0 = __ldg((const float4*)p);
    float4 v1 = __ldg((const float4*)(p + 4));
    uint4 H, L;
    cvt_split2(v0.x, v0.y, H.x, L.x);
    cvt_split2(v0.z, v0.w, H.y, L.y);
    cvt_split2(v1.x, v1.y, H.z, L.z);
    cvt_split2(v1.z, v1.w, H.w, L.w);
    uint32_t off = c * 16384 + SW128((uint32_t)(n * 128 + g * 16));
    *(uint4*)(g_bhi + off) = H;
    *(uint4*)(g_blo + off) = L;
}

// ---------------- kernel 3a: x scatter, 8 edges/warp ----------------
__global__ void edge_x_kernel(const void* __restrict__ ei_raw,
                              const float* __restrict__ x) {
    int warp = (blockIdx.x * blockDim.x + threadIdx.x) >> 5;
    int lane = threadIdx.x & 31;
    size_t e0 = (size_t)warp * 8;
    if (e0 >= N_EDGES) return;

    int v = 0;
    if (lane < 8)       v = load_idx(ei_raw, e0 + lane);
    else if (lane < 16) v = load_idx(ei_raw, (size_t)N_EDGES + e0 + (lane - 8));

    int rows[8], cols[8];
#pragma unroll
    for (int i = 0; i < 8; i++) {
        rows[i] = __shfl_sync(0xffffffffu, v, i);
        cols[i] = __shfl_sync(0xffffffffu, v, 8 + i);
    }
    float4 vx[8];
#pragma unroll
    for (int i = 0; i < 8; i++) {
        int c = ((unsigned)cols[i] < N_NODES) ? cols[i] : 0;
        vx[i] = __ldg(&((const float4*)(x + (size_t)c * IN_CH))[lane]);
    }
#pragma unroll
    for (int i = 0; i < 8; i++) {
        if ((unsigned)rows[i] >= N_NODES || (unsigned)cols[i] >= N_NODES) continue;
        red_add_v4(g_agg + (size_t)rows[i] * AGG_W + lane * 4, vx[i]);
    }
    if (lane < 8 && (unsigned)rows[lane] < N_NODES)
        atomicAdd(&g_deg[rows[lane]], 1.0f);
}

// ---------------- kernel 3b: tf scatter, 8 edges/warp (MLP=4) ----------------
__global__ void edge_t_kernel(const void* __restrict__ ei_raw,
                              const float* __restrict__ tf) {
    int warp = (blockIdx.x * blockDim.x + threadIdx.x) >> 5;
    int lane = threadIdx.x & 31;
    size_t e0 = (size_t)warp * 8;
    if (e0 >= N_EDGES) return;
    int half = lane >> 4;
    int l = lane & 15;

    int v = 0;
    if (lane < 8) v = load_idx(ei_raw, e0 + lane);
    int rows[4];
    size_t edges[4];
#pragma unroll
    for (int p = 0; p < 4; p++) {
        edges[p] = e0 + 2 * p + half;
        rows[p] = __shfl_sync(0xffffffffu, v, 2 * p + half);
    }
    float4 vt[4];
#pragma unroll
    for (int p = 0; p < 4; p++)
        vt[p] = __ldg(&((const float4*)tf)[edges[p] * (T_DIM / 4) + l]);
#pragma unroll
    for (int p = 0; p < 4; p++) {
        if ((unsigned)rows[p] >= N_NODES) continue;
        red_add_v4(g_agg + (size_t)rows[p] * AGG_W + IN_CH + l * 4, vt[p]);
    }
}

// ---------------- kernel 4: mma.sync GEMM, 256 threads, interleaved stage ----
// C[100000][128] = relu( A[100000][320] @ B^T + Wsb + deg * cb )
#define KCH 64
#define NCHUNK 5
#define BUF_SZ 65536          // AHI|ALO|BHI|BLO, 16KB each
#define SMEM_SZ (2 * BUF_SZ)

struct StageA { float4 a[8]; };   // per-thread staged A (256 threads)

__device__ __forceinline__ void load_a(StageA& s, int c, int m0, int tid,
                                       const float* __restrict__ x) {
    int gk0 = c * KCH;
#pragma unroll
    for (int it = 0; it < 4; it++) {
        int task = tid + it * 256;
        int m = task >> 3, gg = task & 7;
        int node = m0 + m;
        int gk = gk0 + gg * 8;
        float4 v0 = make_float4(0, 0, 0, 0), v1 = v0;
        if (node < N_NODES) {
            const float* base = (gk < 128)
                ? (x + (size_t)node * IN_CH + gk)
                : (g_agg + (size_t)node * AGG_W + (gk - 128));
            v0 = __ldg((const float4*)base);
            v1 = __ldg((const float4*)(base + 4));
        }
        s.a[it * 2] = v0; s.a[it * 2 + 1] = v1;
    }
}

__device__ __forceinline__ void load_b(uint4* bh, uint4* bl, int c, int tid) {
    const uint4* sh = (const uint4*)(g_bhi + (size_t)c * 16384);
    const uint4* sl = (const uint4*)(g_blo + (size_t)c * 16384);
#pragma unroll
    for (int i = 0; i < 4; i++) {
        bh[i] = __ldg(&sh[tid + i * 256]);
        bl[i] = __ldg(&sl[tid + i * 256]);
    }
}

// store piece p (0..3) of next chunk's data into buf
__device__ __forceinline__ void store_piece(const StageA& s, const uint4* bh,
                                            const uint4* bl, char* buf,
                                            int tid, int p) {
    int task = tid + p * 256;
    int m = task >> 3, gg = task & 7;
    uint32_t off = SW128((uint32_t)(m * 128 + gg * 16));
    float4 v0 = s.a[p * 2], v1 = s.a[p * 2 + 1];
    uint4 H, L;
    cvt_split2(v0.x, v0.y, H.x, L.x);
    cvt_split2(v0.z, v0.w, H.y, L.y);
    cvt_split2(v1.x, v1.y, H.z, L.z);
    cvt_split2(v1.z, v1.w, H.w, L.w);
    *(uint4*)(buf + off) = H;              // AHI
    *(uint4*)(buf + 16384 + off) = L;      // ALO
    ((uint4*)(buf + 32768))[tid + p * 256] = bh[p];   // BHI (raw copy)
    ((uint4*)(buf + 49152))[tid + p * 256] = bl[p];   // BLO
}

__global__ void __launch_bounds__(256, 1)
gemm_mma_kernel(const float* __restrict__ x, const float* __restrict__ Wsb,
                float* __restrict__ out) {
    extern __shared__ char smem[];
    const uint32_t sb = smem_u32(smem);
    const int tid = threadIdx.x;
    const int wid = tid >> 5;
    const int lane = tid & 31;
    const int m0 = blockIdx.x * 128;
    const int wm = (wid >> 2) * 64;   // warp m offset: 0 or 64
    const int wn = (wid & 3) * 32;    // warp n offset: 0,32,64,96
    const int g = lane >> 2;
    const int t = lane & 3;

    float acc[4][4][4];
#pragma unroll
    for (int i = 0; i < 4; i++)
#pragma unroll
        for (int j = 0; j < 4; j++)
#pragma unroll
            for (int r = 0; r < 4; r++) acc[i][j][r] = 0.f;

    StageA st;
    uint4 bh[4], bl[4];
    load_a(st, 0, m0, tid, x);
    load_b(bh, bl, 0, tid);
#pragma unroll
    for (int p = 0; p < 4; p++) store_piece(st, bh, bl, smem, tid, p);
    __syncthreads();

    for (int c = 0; c < NCHUNK; c++) {
        bool more = (c + 1 < NCHUNK);
        if (more) {
            load_a(st, c + 1, m0, tid, x);   // LDGs fly over this chunk's MMAs
            load_b(bh, bl, c + 1, tid);
        }
        uint32_t base = sb + (c & 1) * BUF_SZ;
        char* nextbuf = smem + ((c + 1) & 1) * BUF_SZ;

#pragma unroll
        for (int ks = 0; ks < 4; ks++) {
            int kk = ks * 16;
            uint32_t a_hi[4][4], a_lo[4][4];
#pragma unroll
            for (int mi = 0; mi < 4; mi++) {
                int mrow = wm + mi * 16;
                int r = mrow + (lane & 7) + ((lane & 8) ? 8 : 0);
                int kb = (kk + ((lane & 16) ? 8 : 0)) * 2;
                uint32_t off = SW128((uint32_t)(r * 128 + kb));
                ldmx4(base + off, a_hi[mi][0], a_hi[mi][1], a_hi[mi][2], a_hi[mi][3]);
                ldmx4(base + 16384 + off, a_lo[mi][0], a_lo[mi][1], a_lo[mi][2], a_lo[mi][3]);
            }
            uint32_t b_hi[4][2], b_lo[4][2];
#pragma unroll
            for (int nh = 0; nh < 2; nh++) {
                int n0 = wn + nh * 16;
                int r = n0 + (lane & 7) + ((lane & 16) ? 8 : 0);
                int kb = (kk + ((lane & 8) ? 8 : 0)) * 2;
                uint32_t off = SW128((uint32_t)(r * 128 + kb));
                uint32_t q0, q1, q2, q3;
                ldmx4(base + 32768 + off, q0, q1, q2, q3);
                b_hi[nh * 2][0] = q0; b_hi[nh * 2][1] = q1;
                b_hi[nh * 2 + 1][0] = q2; b_hi[nh * 2 + 1][1] = q3;
                ldmx4(base + 49152 + off, q0, q1, q2, q3);
                b_lo[nh * 2][0] = q0; b_lo[nh * 2][1] = q1;
                b_lo[nh * 2 + 1][0] = q2; b_lo[nh * 2 + 1][1] = q3;
            }
#pragma unroll
            for (int mi = 0; mi < 4; mi++)
#pragma unroll
                for (int ni = 0; ni < 4; ni++) {
                    mma_bf16(acc[mi][ni], a_hi[mi], b_hi[ni]);
                    mma_bf16(acc[mi][ni], a_lo[mi], b_hi[ni]);
                    mma_bf16(acc[mi][ni], a_hi[mi], b_lo[ni]);
                }
            if (more) store_piece(st, bh, bl, nextbuf, tid, ks);  // hide cvt under MMA
        }
        if (more) __syncthreads();
    }

    // ---- epilogue: bias + deg*cb + relu, store ----
#pragma unroll
    for (int mi = 0; mi < 4; mi++) {
        int row0 = m0 + wm + mi * 16 + g;
        int row1 = row0 + 8;
        float d0 = (row0 < N_NODES) ? g_deg[row0] : 0.f;
        float d1 = (row1 < N_NODES) ? g_deg[row1] : 0.f;
#pragma unroll
        for (int ni = 0; ni < 4; ni++) {
            int cn = wn + ni * 8 + t * 2;
            float2 bs = *(const float2*)(Wsb + cn);
            float2 cb = *(const float2*)(g_cb + cn);
            if (row0 < N_NODES) {
                float2 o;
                o.x = fmaxf(acc[mi][ni][0] + bs.x + d0 * cb.x, 0.f);
                o.y = fmaxf(acc[mi][ni][1] + bs.y + d0 * cb.y, 0.f);
                *(float2*)(out + (size_t)row0 * OUT_CH + cn) = o;
            }
            if (row1 < N_NODES) {
                float2 o;
                o.x = fmaxf(acc[mi][ni][2] + bs.x + d1 * cb.x, 0.f);
                o.y = fmaxf(acc[mi][ni][3] + bs.y + d1 * cb.y, 0.f);
                *(float2*)(out + (size_t)row1 * OUT_CH + cn) = o;
            }
        }
    }
}

// ---------------- launcher ----------------
extern "C" void kernel_launch(void* const* d_in, const int* in_sizes, int n_in,
                              void* d_out, int out_size) {
    const float* x = nullptr; const void* ei = nullptr; const float* tf = nullptr;
    const float* Wsw = nullptr; const float* Wsb = nullptr;
    const float* Wtw = nullptr; const float* Wtb = nullptr;
    const float* Tw = nullptr;  const float* Tb = nullptr;
    int n16384 = 0, n128 = 0;
    for (int i = 0; i < n_in; i++) {
        long long s = in_sizes[i];
        void* p = d_in[i];
        if (s == (long long)N_NODES * IN_CH)      x  = (const float*)p;
        else if (s == 2LL * N_EDGES)              ei = (const void*)p;
        else if (s == (long long)N_EDGES * T_DIM) tf = (const float*)p;
        else if (s == OUT_CH * T_DIM)             Tw = (const float*)p;
        else if (s == OUT_CH * IN_CH) {
            if (n16384++ == 0) Wsw = (const float*)p; else Wtw = (const float*)p;
        } else if (s == OUT_CH) {
            if (n128 == 0) Wsb = (const float*)p;
            else if (n128 == 1) Wtb = (const float*)p;
            else Tb = (const float*)p;
            n128++;
        }
    }
    float* out = (float*)d_out;

    cudaFuncSetAttribute(gemm_mma_kernel,
                         cudaFuncAttributeMaxDynamicSharedMemorySize, SMEM_SZ);

    // zero accumulators via memset nodes (driver-rate, graph-capturable)
    void* agg_ptr = nullptr; void* deg_ptr = nullptr;
    cudaGetSymbolAddress(&agg_ptr, g_agg);
    cudaGetSymbolAddress(&deg_ptr, g_deg);
    cudaMemsetAsync(agg_ptr, 0, sizeof(float) * (size_t)N_NODES * AGG_W);
    cudaMemsetAsync(deg_ptr, 0, sizeof(float) * N_NODES);

    detect_kernel<<<1, 256>>>((const int*)ei);
    prep_kernel<<<1, 128>>>(Wtb, Tb);
    prep_b_kernel<<<20, 256>>>(Wsw, Wtw, Tw);
    edge_t_kernel<<<N_EDGES / 64, 256>>>(ei, tf);  // tf stream first
    edge_x_kernel<<<N_EDGES / 64, 256>>>(ei, x);   // leaves x/agg hot for GEMM
    gemm_mma_kernel<<<(N_NODES + 127) / 128, 256, SMEM_SZ>>>(x, Wsb, out);
}

// round 13
// speedup vs baseline: 1.0617x; 1.0617x over previous
#include <cuda_runtime.h>
#include <cuda_fp16.h>
#include <cstdint>

#define N_NODES 100000
#define N_EDGES 1000000
#define IN_CH   128
#define OUT_CH  128
#define T_DIM   64
#define AGG_W   192

// ---------------- device scratch ----------------
__device__ __align__(16) float g_agg[(size_t)N_NODES * AGG_W];
__device__ __align__(16) float g_deg[N_NODES];
__device__ __align__(16) float g_cb[128];                 // W_T_b + T_b
__device__ __align__(16) unsigned char g_bhi[5 * 16384];  // B fp16, pre-swizzled chunks
__device__ int g_idx_is64;

// ---------------- generic helpers ----------------
__device__ __forceinline__ void red_add_v4(float* p, float4 v) {
    unsigned long long gp = __cvta_generic_to_global((void*)p);
    asm volatile("red.global.add.v4.f32 [%0], {%1,%2,%3,%4};"
                 :: "l"(gp), "f"(v.x), "f"(v.y), "f"(v.z), "f"(v.w)
                 : "memory");
}
__device__ __forceinline__ uint32_t smem_u32(const void* p) {
    uint32_t a;
    asm("{ .reg .u64 t; cvta.to.shared.u64 t, %1; cvt.u32.u64 %0, t; }"
        : "=r"(a) : "l"(p));
    return a;
}
#define SW128(o) ((o) ^ (((o) >> 3) & 0x70))

__device__ __forceinline__ void ldmx4(uint32_t addr, uint32_t& r0, uint32_t& r1,
                                      uint32_t& r2, uint32_t& r3) {
    asm volatile("ldmatrix.sync.aligned.m8n8.x4.shared.b16 {%0,%1,%2,%3}, [%4];"
                 : "=r"(r0), "=r"(r1), "=r"(r2), "=r"(r3) : "r"(addr));
}
__device__ __forceinline__ void mma_f16(float* c, const uint32_t* a, const uint32_t* b) {
    asm volatile("mma.sync.aligned.m16n8k16.row.col.f32.f16.f16.f32 "
                 "{%0,%1,%2,%3}, {%4,%5,%6,%7}, {%8,%9}, {%0,%1,%2,%3};"
                 : "+f"(c[0]), "+f"(c[1]), "+f"(c[2]), "+f"(c[3])
                 : "r"(a[0]), "r"(a[1]), "r"(a[2]), "r"(a[3]), "r"(b[0]), "r"(b[1]));
}
// fp16 2-term split of a pair of floats: h = fp16(v), l = fp16(v - h)
__device__ __forceinline__ void cvt_split2(float a, float b, uint32_t& h, uint32_t& l) {
    __half2 hb = __floats2half2_rn(a, b);
    float2 hf = __half22float2(hb);
    __half2 lb = __floats2half2_rn(a - hf.x, b - hf.y);
    h = *(uint32_t*)&hb;
    l = *(uint32_t*)&lb;
}

// ---------------- kernel 0: detect edge_index dtype ----------------
__global__ void detect_kernel(const int* __restrict__ ei_raw) {
    __shared__ int any_nonzero;
    if (threadIdx.x == 0) any_nonzero = 0;
    __syncthreads();
    for (int i = threadIdx.x; i < 4096; i += blockDim.x)
        if (ei_raw[2 * i + 1] != 0) any_nonzero = 1;
    __syncthreads();
    if (threadIdx.x == 0) g_idx_is64 = (any_nonzero == 0);
}
__device__ __forceinline__ int load_idx(const void* ei_raw, size_t pos) {
    if (g_idx_is64) return (int)__ldg(&((const long long*)ei_raw)[pos]);
    return __ldg(&((const int*)ei_raw)[pos]);
}

// ---------------- kernel 1: combined bias ----------------
__global__ void prep_kernel(const float* __restrict__ Wtb, const float* __restrict__ Tb) {
    int tid = threadIdx.x;
    if (tid < 128) g_cb[tid] = Wtb[tid] + Tb[tid];
}

// ---------------- kernel 1b: precompute B fp16 chunk images ----------------
__global__ void prep_b_kernel(const float* __restrict__ Wsw,
                              const float* __restrict__ Wtw,
                              const float* __restrict__ Tw) {
    int t = blockIdx.x * blockDim.x + threadIdx.x;
    if (t >= 5 * 1024) return;
    int c = t >> 10, rem = t & 1023;
    int n = rem >> 3, g = rem & 7;
    const float* bbase; int bstride;
    if (c < 2)      { bbase = Wsw + c * 64;       bstride = 128; }
    else if (c < 4) { bbase = Wtw + (c - 2) * 64; bstride = 128; }
    else            { bbase = Tw;                 bstride = 64;  }
    const float* p = bbase + (size_t)n * bstride + g * 8;
    float4 v0 = __ldg((const float4*)p);
    float4 v1 = __ldg((const float4*)(p + 4));
    uint4 H;
    __half2 h;
    h = __floats2half2_rn(v0.x, v0.y); H.x = *(uint32_t*)&h;
    h = __floats2half2_rn(v0.z, v0.w); H.y = *(uint32_t*)&h;
    h = __floats2half2_rn(v1.x, v1.y); H.z = *(uint32_t*)&h;
    h = __floats2half2_rn(v1.z, v1.w); H.w = *(uint32_t*)&h;
    uint32_t off = c * 16384 + SW128((uint32_t)(n * 128 + g * 16));
    *(uint4*)(g_bhi + off) = H;
}

// ---------------- kernel 3a: x scatter, 8 edges/warp ----------------
__global__ void edge_x_kernel(const void* __restrict__ ei_raw,
                              const float* __restrict__ x) {
    int warp = (blockIdx.x * blockDim.x + threadIdx.x) >> 5;
    int lane = threadIdx.x & 31;
    size_t e0 = (size_t)warp * 8;
    if (e0 >= N_EDGES) return;

    int v = 0;
    if (lane < 8)       v = load_idx(ei_raw, e0 + lane);
    else if (lane < 16) v = load_idx(ei_raw, (size_t)N_EDGES + e0 + (lane - 8));

    int rows[8], cols[8];
#pragma unroll
    for (int i = 0; i < 8; i++) {
        rows[i] = __shfl_sync(0xffffffffu, v, i);
        cols[i] = __shfl_sync(0xffffffffu, v, 8 + i);
    }
    float4 vx[8];
#pragma unroll
    for (int i = 0; i < 8; i++) {
        int c = ((unsigned)cols[i] < N_NODES) ? cols[i] : 0;
        vx[i] = __ldg(&((const float4*)(x + (size_t)c * IN_CH))[lane]);
    }
#pragma unroll
    for (int i = 0; i < 8; i++) {
        if ((unsigned)rows[i] >= N_NODES || (unsigned)cols[i] >= N_NODES) continue;
        red_add_v4(g_agg + (size_t)rows[i] * AGG_W + lane * 4, vx[i]);
    }
    if (lane < 8 && (unsigned)rows[lane] < N_NODES)
        atomicAdd(&g_deg[rows[lane]], 1.0f);
}

// ---------------- kernel 3b: tf scatter, 8 edges/warp (MLP=4) ----------------
__global__ void edge_t_kernel(const void* __restrict__ ei_raw,
                              const float* __restrict__ tf) {
    int warp = (blockIdx.x * blockDim.x + threadIdx.x) >> 5;
    int lane = threadIdx.x & 31;
    size_t e0 = (size_t)warp * 8;
    if (e0 >= N_EDGES) return;
    int half = lane >> 4;
    int l = lane & 15;

    int v = 0;
    if (lane < 8) v = load_idx(ei_raw, e0 + lane);
    int rows[4];
    size_t edges[4];
#pragma unroll
    for (int p = 0; p < 4; p++) {
        edges[p] = e0 + 2 * p + half;
        rows[p] = __shfl_sync(0xffffffffu, v, 2 * p + half);
    }
    float4 vt[4];
#pragma unroll
    for (int p = 0; p < 4; p++)
        vt[p] = __ldg(&((const float4*)tf)[edges[p] * (T_DIM / 4) + l]);
#pragma unroll
    for (int p = 0; p < 4; p++) {
        if ((unsigned)rows[p] >= N_NODES) continue;
        red_add_v4(g_agg + (size_t)rows[p] * AGG_W + IN_CH + l * 4, vt[p]);
    }
}

// ---------------- kernel 4: mma.sync fp16 2-term GEMM, 256 threads ----------
// C[100000][128] = relu( A[100000][320] @ B^T + Wsb + deg * cb )
// A = ah + al (fp16 split, exact to ~2^-22); B = fp16(B) (error 2^-12 -> rel_err ~2e-4)
#define KCH 64
#define NCHUNK 5
#define BUF_SZ 49152          // AHI | ALO | BHI, 16KB each
#define SMEM_SZ (2 * BUF_SZ)  // 96KB double-buffered

struct StageA { float4 a[8]; };

__device__ __forceinline__ void load_a(StageA& s, int c, int m0, int tid,
                                       const float* __restrict__ x) {
    int gk0 = c * KCH;
#pragma unroll
    for (int it = 0; it < 4; it++) {
        int task = tid + it * 256;
        int m = task >> 3, gg = task & 7;
        int node = m0 + m;
        int gk = gk0 + gg * 8;
        float4 v0 = make_float4(0, 0, 0, 0), v1 = v0;
        if (node < N_NODES) {
            const float* base = (gk < 128)
                ? (x + (size_t)node * IN_CH + gk)
                : (g_agg + (size_t)node * AGG_W + (gk - 128));
            v0 = __ldg((const float4*)base);
            v1 = __ldg((const float4*)(base + 4));
        }
        s.a[it * 2] = v0; s.a[it * 2 + 1] = v1;
    }
}

__device__ __forceinline__ void load_b(uint4* bh, int c, int tid) {
    const uint4* sh = (const uint4*)(g_bhi + (size_t)c * 16384);
#pragma unroll
    for (int i = 0; i < 4; i++) bh[i] = __ldg(&sh[tid + i * 256]);
}

__device__ __forceinline__ void store_piece(const StageA& s, const uint4* bh,
                                            char* buf, int tid, int p) {
    int task = tid + p * 256;
    int m = task >> 3, gg = task & 7;
    uint32_t off = SW128((uint32_t)(m * 128 + gg * 16));
    float4 v0 = s.a[p * 2], v1 = s.a[p * 2 + 1];
    uint4 H, L;
    cvt_split2(v0.x, v0.y, H.x, L.x);
    cvt_split2(v0.z, v0.w, H.y, L.y);
    cvt_split2(v1.x, v1.y, H.z, L.z);
    cvt_split2(v1.z, v1.w, H.w, L.w);
    *(uint4*)(buf + off) = H;              // AHI
    *(uint4*)(buf + 16384 + off) = L;      // ALO
    ((uint4*)(buf + 32768))[tid + p * 256] = bh[p];   // BHI raw copy
}

__global__ void __launch_bounds__(256, 1)
gemm_mma_kernel(const float* __restrict__ x, const float* __restrict__ Wsb,
                float* __restrict__ out) {
    extern __shared__ char smem[];
    const uint32_t sb = smem_u32(smem);
    const int tid = threadIdx.x;
    const int wid = tid >> 5;
    const int lane = tid & 31;
    const int m0 = blockIdx.x * 128;
    const int wm = (wid >> 2) * 64;
    const int wn = (wid & 3) * 32;
    const int g = lane >> 2;
    const int t = lane & 3;

    float acc[4][4][4];
#pragma unroll
    for (int i = 0; i < 4; i++)
#pragma unroll
        for (int j = 0; j < 4; j++)
#pragma unroll
            for (int r = 0; r < 4; r++) acc[i][j][r] = 0.f;

    StageA st;
    uint4 bh[4];
    load_a(st, 0, m0, tid, x);
    load_b(bh, 0, tid);
#pragma unroll
    for (int p = 0; p < 4; p++) store_piece(st, bh, smem, tid, p);
    __syncthreads();

    for (int c = 0; c < NCHUNK; c++) {
        bool more = (c + 1 < NCHUNK);
        if (more) {
            load_a(st, c + 1, m0, tid, x);
            load_b(bh, c + 1, tid);
        }
        uint32_t base = sb + (c & 1) * BUF_SZ;
        char* nextbuf = smem + ((c + 1) & 1) * BUF_SZ;

#pragma unroll
        for (int ks = 0; ks < 4; ks++) {
            int kk = ks * 16;
            uint32_t a_hi[4][4], a_lo[4][4];
#pragma unroll
            for (int mi = 0; mi < 4; mi++) {
                int mrow = wm + mi * 16;
                int r = mrow + (lane & 7) + ((lane & 8) ? 8 : 0);
                int kb = (kk + ((lane & 16) ? 8 : 0)) * 2;
                uint32_t off = SW128((uint32_t)(r * 128 + kb));
                ldmx4(base + off, a_hi[mi][0], a_hi[mi][1], a_hi[mi][2], a_hi[mi][3]);
                ldmx4(base + 16384 + off, a_lo[mi][0], a_lo[mi][1], a_lo[mi][2], a_lo[mi][3]);
            }
            uint32_t b_hi[4][2];
#pragma unroll
            for (int nh = 0; nh < 2; nh++) {
                int n0 = wn + nh * 16;
                int r = n0 + (lane & 7) + ((lane & 16) ? 8 : 0);
                int kb = (kk + ((lane & 8) ? 8 : 0)) * 2;
                uint32_t off = SW128((uint32_t)(r * 128 + kb));
                uint32_t q0, q1, q2, q3;
                ldmx4(base + 32768 + off, q0, q1, q2, q3);
                b_hi[nh * 2][0] = q0; b_hi[nh * 2][1] = q1;
                b_hi[nh * 2 + 1][0] = q2; b_hi[nh * 2 + 1][1] = q3;
            }
#pragma unroll
            for (int mi = 0; mi < 4; mi++)
#pragma unroll
                for (int ni = 0; ni < 4; ni++) {
                    mma_f16(acc[mi][ni], a_hi[mi], b_hi[ni]);
                    mma_f16(acc[mi][ni], a_lo[mi], b_hi[ni]);
                }
            if (more) store_piece(st, bh, nextbuf, tid, ks);
        }
        if (more) __syncthreads();
    }

    // ---- epilogue: bias + deg*cb + relu, store ----
#pragma unroll
    for (int mi = 0; mi < 4; mi++) {
        int row0 = m0 + wm + mi * 16 + g;
        int row1 = row0 + 8;
        float d0 = (row0 < N_NODES) ? g_deg[row0] : 0.f;
        float d1 = (row1 < N_NODES) ? g_deg[row1] : 0.f;
#pragma unroll
        for (int ni = 0; ni < 4; ni++) {
            int cn = wn + ni * 8 + t * 2;
            float2 bs = *(const float2*)(Wsb + cn);
            float2 cb = *(const float2*)(g_cb + cn);
            if (row0 < N_NODES) {
                float2 o;
                o.x = fmaxf(acc[mi][ni][0] + bs.x + d0 * cb.x, 0.f);
                o.y = fmaxf(acc[mi][ni][1] + bs.y + d0 * cb.y, 0.f);
                *(float2*)(out + (size_t)row0 * OUT_CH + cn) = o;
            }
            if (row1 < N_NODES) {
                float2 o;
                o.x = fmaxf(acc[mi][ni][2] + bs.x + d1 * cb.x, 0.f);
                o.y = fmaxf(acc[mi][ni][3] + bs.y + d1 * cb.y, 0.f);
                *(float2*)(out + (size_t)row1 * OUT_CH + cn) = o;
            }
        }
    }
}

// ---------------- launcher ----------------
extern "C" void kernel_launch(void* const* d_in, const int* in_sizes, int n_in,
                              void* d_out, int out_size) {
    const float* x = nullptr; const void* ei = nullptr; const float* tf = nullptr;
    const float* Wsw = nullptr; const float* Wsb = nullptr;
    const float* Wtw = nullptr; const float* Wtb = nullptr;
    const float* Tw = nullptr;  const float* Tb = nullptr;
    int n16384 = 0, n128 = 0;
    for (int i = 0; i < n_in; i++) {
        long long s = in_sizes[i];
        void* p = d_in[i];
        if (s == (long long)N_NODES * IN_CH)      x  = (const float*)p;
        else if (s == 2LL * N_EDGES)              ei = (const void*)p;
        else if (s == (long long)N_EDGES * T_DIM) tf = (const float*)p;
        else if (s == OUT_CH * T_DIM)             Tw = (const float*)p;
        else if (s == OUT_CH * IN_CH) {
            if (n16384++ == 0) Wsw = (const float*)p; else Wtw = (const float*)p;
        } else if (s == OUT_CH) {
            if (n128 == 0) Wsb = (const float*)p;
            else if (n128 == 1) Wtb = (const float*)p;
            else Tb = (const float*)p;
            n128++;
        }
    }
    float* out = (float*)d_out;

    cudaFuncSetAttribute(gemm_mma_kernel,
                         cudaFuncAttributeMaxDynamicSharedMemorySize, SMEM_SZ);

    void* agg_ptr = nullptr; void* deg_ptr = nullptr;
    cudaGetSymbolAddress(&agg_ptr, g_agg);
    cudaGetSymbolAddress(&deg_ptr, g_deg);
    cudaMemsetAsync(agg_ptr, 0, sizeof(float) * (size_t)N_NODES * AGG_W);
    cudaMemsetAsync(deg_ptr, 0, sizeof(float) * N_NODES);

    detect_kernel<<<1, 256>>>((const int*)ei);
    prep_kernel<<<1, 128>>>(Wtb, Tb);
    prep_b_kernel<<<20, 256>>>(Wsw, Wtw, Tw);
    edge_t_kernel<<<N_EDGES / 64, 256>>>(ei, tf);
    edge_x_kernel<<<N_EDGES / 64, 256>>>(ei, x);
    gemm_mma_kernel<<<(N_NODES + 127) / 128, 256, SMEM_SZ>>>(x, Wsb, out);
}

// round 14
// speedup vs baseline: 1.1302x; 1.0646x over previous
#include <cuda_runtime.h>
#include <cuda_fp16.h>
#include <cstdint>

#define N_NODES 100000
#define N_EDGES 1000000
#define IN_CH   128
#define OUT_CH  128
#define T_DIM   64
#define AGG_W   192

// ---------------- device scratch ----------------
__device__ __align__(16) float g_agg[(size_t)N_NODES * AGG_W];
__device__ __align__(16) float g_deg[N_NODES];
__device__ __align__(16) float g_cb[128];                 // W_T_b + T_b
__device__ __align__(16) unsigned char g_bhi[5 * 16384];  // B fp16, pre-swizzled chunks
__device__ int g_idx_is64;

// ---------------- generic helpers ----------------
__device__ __forceinline__ void red_add_v4(float* p, float4 v) {
    unsigned long long gp = __cvta_generic_to_global((void*)p);
    asm volatile("red.global.add.v4.f32 [%0], {%1,%2,%3,%4};"
                 :: "l"(gp), "f"(v.x), "f"(v.y), "f"(v.z), "f"(v.w)
                 : "memory");
}
__device__ __forceinline__ uint32_t smem_u32(const void* p) {
    uint32_t a;
    asm("{ .reg .u64 t; cvta.to.shared.u64 t, %1; cvt.u32.u64 %0, t; }"
        : "=r"(a) : "l"(p));
    return a;
}
#define SW128(o) ((o) ^ (((o) >> 3) & 0x70))

__device__ __forceinline__ void ldmx4(uint32_t addr, uint32_t& r0, uint32_t& r1,
                                      uint32_t& r2, uint32_t& r3) {
    asm volatile("ldmatrix.sync.aligned.m8n8.x4.shared.b16 {%0,%1,%2,%3}, [%4];"
                 : "=r"(r0), "=r"(r1), "=r"(r2), "=r"(r3) : "r"(addr));
}
__device__ __forceinline__ void mma_f16(float* c, const uint32_t* a, const uint32_t* b) {
    asm volatile("mma.sync.aligned.m16n8k16.row.col.f32.f16.f16.f32 "
                 "{%0,%1,%2,%3}, {%4,%5,%6,%7}, {%8,%9}, {%0,%1,%2,%3};"
                 : "+f"(c[0]), "+f"(c[1]), "+f"(c[2]), "+f"(c[3])
                 : "r"(a[0]), "r"(a[1]), "r"(a[2]), "r"(a[3]), "r"(b[0]), "r"(b[1]));
}
__device__ __forceinline__ uint32_t pack_h2(float a, float b) {
    __half2 h = __floats2half2_rn(a, b);
    return *(uint32_t*)&h;
}

// ---------------- kernel 0: detect edge_index dtype ----------------
__global__ void detect_kernel(const int* __restrict__ ei_raw) {
    __shared__ int any_nonzero;
    if (threadIdx.x == 0) any_nonzero = 0;
    __syncthreads();
    for (int i = threadIdx.x; i < 4096; i += blockDim.x)
        if (ei_raw[2 * i + 1] != 0) any_nonzero = 1;
    __syncthreads();
    if (threadIdx.x == 0) g_idx_is64 = (any_nonzero == 0);
}
__device__ __forceinline__ int load_idx(const void* ei_raw, size_t pos) {
    if (g_idx_is64) return (int)__ldg(&((const long long*)ei_raw)[pos]);
    return __ldg(&((const int*)ei_raw)[pos]);
}

// ---------------- kernel 1: combined bias ----------------
__global__ void prep_kernel(const float* __restrict__ Wtb, const float* __restrict__ Tb) {
    int tid = threadIdx.x;
    if (tid < 128) g_cb[tid] = Wtb[tid] + Tb[tid];
}

// ---------------- kernel 1b: precompute B fp16 chunk images ----------------
__global__ void prep_b_kernel(const float* __restrict__ Wsw,
                              const float* __restrict__ Wtw,
                              const float* __restrict__ Tw) {
    int t = blockIdx.x * blockDim.x + threadIdx.x;
    if (t >= 5 * 1024) return;
    int c = t >> 10, rem = t & 1023;
    int n = rem >> 3, g = rem & 7;
    const float* bbase; int bstride;
    if (c < 2)      { bbase = Wsw + c * 64;       bstride = 128; }
    else if (c < 4) { bbase = Wtw + (c - 2) * 64; bstride = 128; }
    else            { bbase = Tw;                 bstride = 64;  }
    const float* p = bbase + (size_t)n * bstride + g * 8;
    float4 v0 = __ldg((const float4*)p);
    float4 v1 = __ldg((const float4*)(p + 4));
    uint4 H;
    H.x = pack_h2(v0.x, v0.y);
    H.y = pack_h2(v0.z, v0.w);
    H.z = pack_h2(v1.x, v1.y);
    H.w = pack_h2(v1.z, v1.w);
    uint32_t off = c * 16384 + SW128((uint32_t)(n * 128 + g * 16));
    *(uint4*)(g_bhi + off) = H;
}

// ---------------- kernel 3a: x scatter, 8 edges/warp ----------------
__global__ void edge_x_kernel(const void* __restrict__ ei_raw,
                              const float* __restrict__ x) {
    int warp = (blockIdx.x * blockDim.x + threadIdx.x) >> 5;
    int lane = threadIdx.x & 31;
    size_t e0 = (size_t)warp * 8;
    if (e0 >= N_EDGES) return;

    int v = 0;
    if (lane < 8)       v = load_idx(ei_raw, e0 + lane);
    else if (lane < 16) v = load_idx(ei_raw, (size_t)N_EDGES + e0 + (lane - 8));

    int rows[8], cols[8];
#pragma unroll
    for (int i = 0; i < 8; i++) {
        rows[i] = __shfl_sync(0xffffffffu, v, i);
        cols[i] = __shfl_sync(0xffffffffu, v, 8 + i);
    }
    float4 vx[8];
#pragma unroll
    for (int i = 0; i < 8; i++) {
        int c = ((unsigned)cols[i] < N_NODES) ? cols[i] : 0;
        vx[i] = __ldg(&((const float4*)(x + (size_t)c * IN_CH))[lane]);
    }
#pragma unroll
    for (int i = 0; i < 8; i++) {
        if ((unsigned)rows[i] >= N_NODES || (unsigned)cols[i] >= N_NODES) continue;
        red_add_v4(g_agg + (size_t)rows[i] * AGG_W + lane * 4, vx[i]);
    }
    if (lane < 8 && (unsigned)rows[lane] < N_NODES)
        atomicAdd(&g_deg[rows[lane]], 1.0f);
}

// ---------------- kernel 3b: tf scatter, 8 edges/warp (MLP=4) ----------------
__global__ void edge_t_kernel(const void* __restrict__ ei_raw,
                              const float* __restrict__ tf) {
    int warp = (blockIdx.x * blockDim.x + threadIdx.x) >> 5;
    int lane = threadIdx.x & 31;
    size_t e0 = (size_t)warp * 8;
    if (e0 >= N_EDGES) return;
    int half = lane >> 4;
    int l = lane & 15;

    int v = 0;
    if (lane < 8) v = load_idx(ei_raw, e0 + lane);
    int rows[4];
    size_t edges[4];
#pragma unroll
    for (int p = 0; p < 4; p++) {
        edges[p] = e0 + 2 * p + half;
        rows[p] = __shfl_sync(0xffffffffu, v, 2 * p + half);
    }
    float4 vt[4];
#pragma unroll
    for (int p = 0; p < 4; p++)
        vt[p] = __ldg(&((const float4*)tf)[edges[p] * (T_DIM / 4) + l]);
#pragma unroll
    for (int p = 0; p < 4; p++) {
        if ((unsigned)rows[p] >= N_NODES) continue;
        red_add_v4(g_agg + (size_t)rows[p] * AGG_W + IN_CH + l * 4, vt[p]);
    }
}

// ---------------- kernel 4: mma.sync fp16 1-term GEMM, 256 threads ----------
// C[100000][128] = relu( A[100000][320] @ B^T + Wsb + deg * cb )
// A = fp16(A), B = fp16(B); errors independent ~2e-4 each, RSS ~2.8e-4 < 1e-3
#define KCH 64
#define NCHUNK 5
#define BUF_SZ 32768          // AHI | BHI, 16KB each
#define SMEM_SZ (2 * BUF_SZ)  // 64KB double-buffered

struct StageA { float4 a[8]; };

__device__ __forceinline__ void load_a(StageA& s, int c, int m0, int tid,
                                       const float* __restrict__ x) {
    int gk0 = c * KCH;
#pragma unroll
    for (int it = 0; it < 4; it++) {
        int task = tid + it * 256;
        int m = task >> 3, gg = task & 7;
        int node = m0 + m;
        int gk = gk0 + gg * 8;
        float4 v0 = make_float4(0, 0, 0, 0), v1 = v0;
        if (node < N_NODES) {
            const float* base = (gk < 128)
                ? (x + (size_t)node * IN_CH + gk)
                : (g_agg + (size_t)node * AGG_W + (gk - 128));
            v0 = __ldg((const float4*)base);
            v1 = __ldg((const float4*)(base + 4));
        }
        s.a[it * 2] = v0; s.a[it * 2 + 1] = v1;
    }
}

__device__ __forceinline__ void load_b(uint4* bh, int c, int tid) {
    const uint4* sh = (const uint4*)(g_bhi + (size_t)c * 16384);
#pragma unroll
    for (int i = 0; i < 4; i++) bh[i] = __ldg(&sh[tid + i * 256]);
}

__device__ __forceinline__ void store_piece(const StageA& s, const uint4* bh,
                                            char* buf, int tid, int p) {
    int task = tid + p * 256;
    int m = task >> 3, gg = task & 7;
    uint32_t off = SW128((uint32_t)(m * 128 + gg * 16));
    float4 v0 = s.a[p * 2], v1 = s.a[p * 2 + 1];
    uint4 H;
    H.x = pack_h2(v0.x, v0.y);
    H.y = pack_h2(v0.z, v0.w);
    H.z = pack_h2(v1.x, v1.y);
    H.w = pack_h2(v1.z, v1.w);
    *(uint4*)(buf + off) = H;                          // AHI
    ((uint4*)(buf + 16384))[tid + p * 256] = bh[p];    // BHI raw copy
}

__global__ void __launch_bounds__(256, 1)
gemm_mma_kernel(const float* __restrict__ x, const float* __restrict__ Wsb,
                float* __restrict__ out) {
    extern __shared__ char smem[];
    const uint32_t sb = smem_u32(smem);
    const int tid = threadIdx.x;
    const int wid = tid >> 5;
    const int lane = tid & 31;
    const int m0 = blockIdx.x * 128;
    const int wm = (wid >> 2) * 64;
    const int wn = (wid & 3) * 32;
    const int g = lane >> 2;
    const int t = lane & 3;

    float acc[4][4][4];
#pragma unroll
    for (int i = 0; i < 4; i++)
#pragma unroll
        for (int j = 0; j < 4; j++)
#pragma unroll
            for (int r = 0; r < 4; r++) acc[i][j][r] = 0.f;

    StageA st;
    uint4 bh[4];
    load_a(st, 0, m0, tid, x);
    load_b(bh, 0, tid);
#pragma unroll
    for (int p = 0; p < 4; p++) store_piece(st, bh, smem, tid, p);
    __syncthreads();

    for (int c = 0; c < NCHUNK; c++) {
        bool more = (c + 1 < NCHUNK);
        if (more) {
            load_a(st, c + 1, m0, tid, x);
            load_b(bh, c + 1, tid);
        }
        uint32_t base = sb + (c & 1) * BUF_SZ;
        char* nextbuf = smem + ((c + 1) & 1) * BUF_SZ;

#pragma unroll
        for (int ks = 0; ks < 4; ks++) {
            int kk = ks * 16;
            uint32_t a_hi[4][4];
#pragma unroll
            for (int mi = 0; mi < 4; mi++) {
                int mrow = wm + mi * 16;
                int r = mrow + (lane & 7) + ((lane & 8) ? 8 : 0);
                int kb = (kk + ((lane & 16) ? 8 : 0)) * 2;
                uint32_t off = SW128((uint32_t)(r * 128 + kb));
                ldmx4(base + off, a_hi[mi][0], a_hi[mi][1], a_hi[mi][2], a_hi[mi][3]);
            }
            uint32_t b_hi[4][2];
#pragma unroll
            for (int nh = 0; nh < 2; nh++) {
                int n0 = wn + nh * 16;
                int r = n0 + (lane & 7) + ((lane & 16) ? 8 : 0);
                int kb = (kk + ((lane & 8) ? 8 : 0)) * 2;
                uint32_t off = SW128((uint32_t)(r * 128 + kb));
                uint32_t q0, q1, q2, q3;
                ldmx4(base + 16384 + off, q0, q1, q2, q3);
                b_hi[nh * 2][0] = q0; b_hi[nh * 2][1] = q1;
                b_hi[nh * 2 + 1][0] = q2; b_hi[nh * 2 + 1][1] = q3;
            }
#pragma unroll
            for (int mi = 0; mi < 4; mi++)
#pragma unroll
                for (int ni = 0; ni < 4; ni++)
                    mma_f16(acc[mi][ni], a_hi[mi], b_hi[ni]);
            if (more) store_piece(st, bh, nextbuf, tid, ks);
        }
        if (more) __syncthreads();
    }

    // ---- epilogue: bias + deg*cb + relu, store ----
#pragma unroll
    for (int mi = 0; mi < 4; mi++) {
        int row0 = m0 + wm + mi * 16 + g;
        int row1 = row0 + 8;
        float d0 = (row0 < N_NODES) ? g_deg[row0] : 0.f;
        float d1 = (row1 < N_NODES) ? g_deg[row1] : 0.f;
#pragma unroll
        for (int ni = 0; ni < 4; ni++) {
            int cn = wn + ni * 8 + t * 2;
            float2 bs = *(const float2*)(Wsb + cn);
            float2 cb = *(const float2*)(g_cb + cn);
            if (row0 < N_NODES) {
                float2 o;
                o.x = fmaxf(acc[mi][ni][0] + bs.x + d0 * cb.x, 0.f);
                o.y = fmaxf(acc[mi][ni][1] + bs.y + d0 * cb.y, 0.f);
                *(float2*)(out + (size_t)row0 * OUT_CH + cn) = o;
            }
            if (row1 < N_NODES) {
                float2 o;
                o.x = fmaxf(acc[mi][ni][2] + bs.x + d1 * cb.x, 0.f);
                o.y = fmaxf(acc[mi][ni][3] + bs.y + d1 * cb.y, 0.f);
                *(float2*)(out + (size_t)row1 * OUT_CH + cn) = o;
            }
        }
    }
}

// ---------------- launcher ----------------
extern "C" void kernel_launch(void* const* d_in, const int* in_sizes, int n_in,
                              void* d_out, int out_size) {
    const float* x = nullptr; const void* ei = nullptr; const float* tf = nullptr;
    const float* Wsw = nullptr; const float* Wsb = nullptr;
    const float* Wtw = nullptr; const float* Wtb = nullptr;
    const float* Tw = nullptr;  const float* Tb = nullptr;
    int n16384 = 0, n128 = 0;
    for (int i = 0; i < n_in; i++) {
        long long s = in_sizes[i];
        void* p = d_in[i];
        if (s == (long long)N_NODES * IN_CH)      x  = (const float*)p;
        else if (s == 2LL * N_EDGES)              ei = (const void*)p;
        else if (s == (long long)N_EDGES * T_DIM) tf = (const float*)p;
        else if (s == OUT_CH * T_DIM)             Tw = (const float*)p;
        else if (s == OUT_CH * IN_CH) {
            if (n16384++ == 0) Wsw = (const float*)p; else Wtw = (const float*)p;
        } else if (s == OUT_CH) {
            if (n128 == 0) Wsb = (const float*)p;
            else if (n128 == 1) Wtb = (const float*)p;
            else Tb = (const float*)p;
            n128++;
        }
    }
    float* out = (float*)d_out;

    cudaFuncSetAttribute(gemm_mma_kernel,
                         cudaFuncAttributeMaxDynamicSharedMemorySize, SMEM_SZ);

    void* agg_ptr = nullptr; void* deg_ptr = nullptr;
    cudaGetSymbolAddress(&agg_ptr, g_agg);
    cudaGetSymbolAddress(&deg_ptr, g_deg);
    cudaMemsetAsync(agg_ptr, 0, sizeof(float) * (size_t)N_NODES * AGG_W);
    cudaMemsetAsync(deg_ptr, 0, sizeof(float) * N_NODES);

    detect_kernel<<<1, 256>>>((const int*)ei);
    prep_kernel<<<1, 128>>>(Wtb, Tb);
    prep_b_kernel<<<20, 256>>>(Wsw, Wtw, Tw);
    edge_t_kernel<<<N_EDGES / 64, 256>>>(ei, tf);
    edge_x_kernel<<<N_EDGES / 64, 256>>>(ei, x);
    gemm_mma_kernel<<<(N_NODES + 127) / 128, 256, SMEM_SZ>>>(x, Wsb, out);
}